// round 7
// baseline (speedup 1.0000x reference)
#include <cuda_runtime.h>
#include <cstdint>

#define BB   32
#define TT   336
#define NH   100
#define NM   150
#define FH   8
#define FM   16
#define HG   64
#define HL   64
#define FUT  24
#define TC   16   // timesteps per precompute block
#define TB   16   // graphs per gnn block

typedef unsigned long long u64;

// d = a*b + d packed (per-lane .rn, bitwise == scalar FFMA)
#define FMA2(d, a, b) \
    asm("fma.rn.f32x2 %0, %1, %2, %0;" : "+l"(d) : "l"(a), "l"(b))
#define PACK2(d, v) \
    asm("mov.b64 %0, {%1, %1};" : "=l"(d) : "r"(__float_as_uint(v)))
#define PACKF2(d, lo, hi) \
    asm("mov.b64 %0, {%1, %2};" : "=l"(d) : "r"(__float_as_uint(lo)), "r"(__float_as_uint(hi)))
#define UNPACK2(lo, hi, x) \
    asm("mov.b64 {%0, %1}, %2;" : "=f"(lo), "=f"(hi) : "l"(x))

// GNN output x: [n][t][b][hg]
__device__ float g_x[(size_t)NH * TT * BB * HG];
// Precomputed x-gates (+bias): [n][t][j=256][b=32]
__device__ float g_gates[(size_t)NH * TT * 256 * BB];

// CSR edge structure (built once per launch, deterministic order)
__device__ int d_off_h[NH], d_deg_h[NH], d_src_h[512];
__device__ int d_off_m[NH], d_deg_m[NH], d_src_m[1024];

// ---------------------------------------------------------------------------
// Kernel A0: build CSR by target node (deterministic, one block).
// ---------------------------------------------------------------------------
__global__ void __launch_bounds__(256) csr_kernel(
    const int* __restrict__ eh, const int* __restrict__ em, int Eh, int Em)
{
    __shared__ int s_src[1024], s_tgt[1024];
    const int tid = threadIdx.x;

    for (int i = tid; i < Eh; i += 256) { s_src[i] = eh[i]; s_tgt[i] = eh[Eh + i]; }
    __syncthreads();
    if (tid < NH) {
        int start = 0;
        for (int e = 0; e < Eh; e++) start += (s_tgt[e] < tid) ? 1 : 0;
        int p = start, cnt = 0;
        for (int e = 0; e < Eh; e++)
            if (s_tgt[e] == tid) { d_src_h[p++] = s_src[e]; cnt++; }
        d_off_h[tid] = start; d_deg_h[tid] = cnt;
    }
    __syncthreads();
    for (int i = tid; i < Em; i += 256) { s_src[i] = em[i]; s_tgt[i] = em[Em + i]; }
    __syncthreads();
    if (tid < NH) {
        int start = 0;
        for (int e = 0; e < Em; e++) start += (s_tgt[e] < tid) ? 1 : 0;
        int p = start, cnt = 0;
        for (int e = 0; e < Em; e++)
            if (s_tgt[e] == tid) { d_src_m[p++] = s_src[e]; cnt++; }
        d_off_m[tid] = start; d_deg_m[tid] = cnt;
    }
}

// ---------------------------------------------------------------------------
// Kernel A: hetero GraphConv, TB graphs per block, CSR gather. (R6, verified)
// ---------------------------------------------------------------------------
__global__ void __launch_bounds__(256) gnn_kernel(
    const float* __restrict__ xm_all, const float* __restrict__ xh_all,
    const float* __restrict__ Wrel_m, const float* __restrict__ brel_m,
    const float* __restrict__ Wroot_m,
    const float* __restrict__ Wrel_h, const float* __restrict__ brel_h,
    const float* __restrict__ Wroot_h)
{
    __shared__ float swh[FH * HG];
    __shared__ float swr[FH * HG];
    __shared__ float swm[FM * HG];
    __shared__ float sb[HG];
    __shared__ int soff_h[NH], sdeg_h[NH], ssrc_h[512];
    __shared__ int soff_m[NH], sdeg_m[NH], ssrc_m[1024];
    __shared__ float sxh[NH * FH];
    __shared__ float sxm[NM * FM];
    __shared__ float sah[NH * FH];
    __shared__ float sam[NH * FM];

    const int tid = threadIdx.x;

    for (int i = tid; i < HG * FH; i += 256) {
        int j = i / FH, k = i % FH;
        swh[k * HG + j] = 0.5f * Wrel_h[i];
        swr[k * HG + j] = 0.5f * (Wroot_h[i] + Wroot_m[i]);
    }
    for (int i = tid; i < HG * FM; i += 256) {
        int j = i / FM, k = i % FM;
        swm[k * HG + j] = 0.5f * Wrel_m[i];
    }
    for (int i = tid; i < HG; i += 256) sb[i] = 0.5f * (brel_h[i] + brel_m[i]);
    for (int i = tid; i < NH; i += 256) {
        soff_h[i] = d_off_h[i]; sdeg_h[i] = d_deg_h[i];
        soff_m[i] = d_off_m[i]; sdeg_m[i] = d_deg_m[i];
    }
    for (int i = tid; i < 512;  i += 256) ssrc_h[i] = d_src_h[i];
    for (int i = tid; i < 1024; i += 256) ssrc_m[i] = d_src_m[i];

    for (int gi = 0; gi < TB; gi++) {
        const int g = blockIdx.x * TB + gi;
        const float* xh = xh_all + (size_t)g * NH * FH;
        const float* xm = xm_all + (size_t)g * NM * FM;

        __syncthreads();
        for (int i = tid; i < NH * FH / 4; i += 256)
            *(float4*)&sxh[i * 4] = *(const float4*)&xh[i * 4];
        for (int i = tid; i < NM * FM / 4; i += 256)
            *(float4*)&sxm[i * 4] = *(const float4*)&xm[i * 4];
        __syncthreads();

        for (int idx = tid; idx < NH * FH; idx += 256) {
            int n = idx >> 3, k = idx & 7;
            int o = soff_h[n], d = sdeg_h[n];
            float s = 0.f;
            for (int e = 0; e < d; e++) s += sxh[ssrc_h[o + e] * FH + k];
            sah[idx] = s;
        }
        for (int idx = tid; idx < NH * FM; idx += 256) {
            int n = idx >> 4, k = idx & 15;
            int o = soff_m[n], d = sdeg_m[n];
            float s = 0.f;
            for (int e = 0; e < d; e++) s += sxm[ssrc_m[o + e] * FM + k];
            sam[idx] = s;
        }
        __syncthreads();

        const int t = g % TT;
        const int b = g / TT;
        for (int idx = tid; idx < NH * HG; idx += 256) {
            int n = idx >> 6, j = idx & 63;
            float acc = sb[j];
            #pragma unroll
            for (int k = 0; k < FH; k++)
                acc += sah[n * FH + k] * swh[k * HG + j]
                     + sxh[n * FH + k] * swr[k * HG + j];
            #pragma unroll
            for (int k = 0; k < FM; k++)
                acc += sam[n * FM + k] * swm[k * HG + j];
            float v = acc > 0.f ? acc : 0.01f * acc;
            g_x[(((size_t)n * TT + t) * BB + b) * HG + j] = v;
        }
    }
}

// ---------------------------------------------------------------------------
// Kernel B: x-gate precompute, (batch-lane, unit-group) mapping.
// Thread: b = tid&31, ug = tid>>5 (0..7) -> units ug*8..ug*8+7, all 4 gates.
// Weights broadcast within warp; x coalesced LDS.32; stores coalesced [j][b].
// ---------------------------------------------------------------------------
#define XG_SW 0                     // repacked W_ih: 16384
#define XG_SB 16384                 // repacked bias: 256
#define XG_SX (16384 + 256)         // sx[k][b] stride 33: 2112
#define XG_FLOATS (XG_SX + 64*33)
#define XG_BYTES  (XG_FLOATS * 4)

__global__ void __launch_bounds__(256, 3) xgemm_kernel(
    const float* __restrict__ W_ih,
    const float* __restrict__ b_ih, const float* __restrict__ b_hh)
{
    extern __shared__ float sm[];
    float* sW2 = sm + XG_SW;   // [k][ug*32 + gg*8 + uu]
    float* sb2 = sm + XG_SB;   // [ug*32 + gg*8 + uu]
    float* sx  = sm + XG_SX;   // [k][b] stride 33

    const int n   = blockIdx.x;
    const int t0  = blockIdx.y * TC;
    const int tid = threadIdx.x;
    const int b   = tid & 31;
    const int ug  = tid >> 5;       // 0..7

    const float* w = W_ih + (size_t)n * 16384;
    for (int i = tid; i < 16384; i += 256) {
        int j = i >> 6, k = i & 63;
        int gg = j >> 6, r = j & 63, ugx = r >> 3, uu = r & 7;
        sW2[k * 256 + ugx * 32 + gg * 8 + uu] = w[i];
    }
    {
        int j = tid;
        int gg = j >> 6, r = j & 63, ugx = r >> 3, uu = r & 7;
        sb2[ugx * 32 + gg * 8 + uu] = b_ih[n * 256 + j] + b_hh[n * 256 + j];
    }

    const int sb_b = tid >> 3;        // staging batch
    const int sb_k = (tid & 7) << 3;  // staging k base

    const float* xbase = g_x + ((size_t)n * TT + t0) * BB * HG;
    float* gbase = g_gates + ((size_t)(n * TT + t0)) * 256 * BB;
    __syncthreads();

    for (int tt = 0; tt < TC; tt++) {
        const float* xt = xbase + (size_t)tt * BB * HG;
        float4 v0 = *(const float4*)&xt[sb_b * HG + sb_k];
        float4 v1 = *(const float4*)&xt[sb_b * HG + sb_k + 4];
        sx[(sb_k + 0) * 33 + sb_b] = v0.x;
        sx[(sb_k + 1) * 33 + sb_b] = v0.y;
        sx[(sb_k + 2) * 33 + sb_b] = v0.z;
        sx[(sb_k + 3) * 33 + sb_b] = v0.w;
        sx[(sb_k + 4) * 33 + sb_b] = v1.x;
        sx[(sb_k + 5) * 33 + sb_b] = v1.y;
        sx[(sb_k + 6) * 33 + sb_b] = v1.z;
        sx[(sb_k + 7) * 33 + sb_b] = v1.w;
        __syncthreads();

        // acc pairs m=0..15: float index f=2m within thread's 32 weights
        u64 acc[16];
        #pragma unroll
        for (int q = 0; q < 8; q++) {
            float4 bv = *(const float4*)&sb2[ug * 32 + 4 * q];
            PACKF2(acc[2 * q + 0], bv.x, bv.y);
            PACKF2(acc[2 * q + 1], bv.z, bv.w);
        }

        #pragma unroll 4
        for (int k = 0; k < 64; k++) {
            u64 xx;
            PACK2(xx, sx[k * 33 + b]);
            const float* wr = &sW2[k * 256 + ug * 32];
            #pragma unroll
            for (int q = 0; q < 8; q++) {
                float4 wv = *(const float4*)&wr[4 * q];
                u64 w0 = *(const u64*)&wv.x;
                u64 w1 = *(const u64*)&wv.z;
                FMA2(acc[2 * q + 0], xx, w0);
                FMA2(acc[2 * q + 1], xx, w1);
            }
        }

        // store: pair m -> j0 = gg*64 + ug*8 + 2*(m&3), gg = m>>2
        float* gt = gbase + (size_t)tt * 256 * BB;
        #pragma unroll
        for (int m = 0; m < 16; m++) {
            int gg = m >> 2, uu0 = 2 * (m & 3);
            int j0 = gg * 64 + ug * 8 + uu0;
            float lo, hi;
            UNPACK2(lo, hi, acc[m]);
            gt[j0 * 32 + b]       = lo;
            gt[(j0 + 1) * 32 + b] = hi;
        }
        __syncthreads();
    }
}

// ---------------------------------------------------------------------------
// Kernel C: recurrent LSTM, 512 threads, (batch-lane, unit-group) mapping.
// Thread: b = tid&31, ug = tid>>5 (0..15) -> units ug*4..ug*4+3, all gates.
// Per k: 1 coalesced h LDS + 4 broadcast weight LDS.128 + 8 FFMA2.
// ---------------------------------------------------------------------------
#define L_SW  0                      // repacked W_hh: 16384
#define L_SH  16384                  // 2 x [u][b] stride 32: 2*2048
#define L_WL  (L_SH + 2*2048)        // 24*64
#define L_BL  (L_WL + 24*64)
#define LS_FLOATS (L_BL + 32)
#define LS_BYTES  (LS_FLOATS * 4)

__device__ __forceinline__ float sigm(float x) {
    return 1.0f / (1.0f + __expf(-x));
}
__device__ __forceinline__ float tanh_fast(float x) {
    float xc = fminf(fmaxf(x, -15.f), 15.f);
    float e = __expf(2.0f * xc);
    return (e - 1.0f) / (e + 1.0f);
}

__global__ void __launch_bounds__(512) lstm_kernel(
    const float* __restrict__ W_hh,
    const float* __restrict__ W_lin, const float* __restrict__ b_lin,
    float* __restrict__ out)
{
    extern __shared__ float sm[];
    float* sW2   = sm + L_SW;    // [k][ug*16 + gg*4 + uu]
    float* sh    = sm + L_SH;    // 2 x [u*32 + b]
    float* sWlin = sm + L_WL;
    float* sblin = sm + L_BL;

    const int n   = blockIdx.x;
    const int tid = threadIdx.x;
    const int b   = tid & 31;
    const int ug  = tid >> 5;    // 0..15

    const float* whh = W_hh + (size_t)n * 16384;
    for (int i = tid; i < 16384; i += 512) {
        int j = i >> 6, k = i & 63;
        int gg = j >> 6, r = j & 63, ugx = r >> 2, uu = r & 3;
        sW2[k * 256 + ugx * 16 + gg * 4 + uu] = whh[i];
    }
    for (int i = tid; i < FUT * HL; i += 512) sWlin[i] = W_lin[i];
    if (tid < FUT) sblin[tid] = b_lin[tid];
    for (int i = tid; i < 2048; i += 512) sh[i] = 0.f;   // h0 (buffer 0)

    float c[4];
    #pragma unroll
    for (int q = 0; q < 4; q++) c[q] = 0.f;

    const float* gptr = g_gates + (size_t)n * TT * 256 * BB;

    // prefetch gates(t=0): 16 coalesced LDG.32
    float gb[16];
    #pragma unroll
    for (int gg = 0; gg < 4; gg++)
        #pragma unroll
        for (int uu = 0; uu < 4; uu++)
            gb[gg * 4 + uu] = gptr[(gg * 64 + ug * 4 + uu) * 32 + b];

    for (int t = 0; t < TT; t++) {
        // acc[gg*2+p] = units (ug*4+2p, ug*4+2p+1) of gate gg
        u64 acc[8];
        #pragma unroll
        for (int gg = 0; gg < 4; gg++) {
            PACKF2(acc[gg * 2 + 0], gb[gg * 4 + 0], gb[gg * 4 + 1]);
            PACKF2(acc[gg * 2 + 1], gb[gg * 4 + 2], gb[gg * 4 + 3]);
        }

        // prefetch gates(t+1) (latency hidden under k-loop)
        if (t + 1 < TT) {
            const float* gnx = gptr + (size_t)(t + 1) * 256 * BB;
            #pragma unroll
            for (int gg = 0; gg < 4; gg++)
                #pragma unroll
                for (int uu = 0; uu < 4; uu++)
                    gb[gg * 4 + uu] = gnx[(gg * 64 + ug * 4 + uu) * 32 + b];
        }

        const float* hb = sh + (t & 1) * 2048;
        float*       hw = sh + ((t + 1) & 1) * 2048;
        __syncthreads();   // h(t) visible

        #pragma unroll 4
        for (int k = 0; k < 64; k++) {
            u64 hx;
            PACK2(hx, hb[k * 32 + b]);
            const float* wr = &sW2[k * 256 + ug * 16];
            #pragma unroll
            for (int gg = 0; gg < 4; gg++) {
                float4 wv = *(const float4*)&wr[gg * 4];
                u64 w0 = *(const u64*)&wv.x;
                u64 w1 = *(const u64*)&wv.z;
                FMA2(acc[gg * 2 + 0], hx, w0);
                FMA2(acc[gg * 2 + 1], hx, w1);
            }
        }

        // cell update (gate order i, f, g, o); 4 units per thread
        #pragma unroll
        for (int p = 0; p < 2; p++) {
            float iv[2], fv[2], gv[2], ov[2];
            UNPACK2(iv[0], iv[1], acc[0 * 2 + p]);
            UNPACK2(fv[0], fv[1], acc[1 * 2 + p]);
            UNPACK2(gv[0], gv[1], acc[2 * 2 + p]);
            UNPACK2(ov[0], ov[1], acc[3 * 2 + p]);
            #pragma unroll
            for (int du = 0; du < 2; du++) {
                int q = 2 * p + du;
                float ig = sigm(iv[du]);
                float fg = sigm(fv[du]);
                float gg = tanh_fast(gv[du]);
                float og = sigm(ov[du]);
                float cc = fg * c[q] + ig * gg;
                c[q] = cc;
                hw[(ug * 4 + q) * 32 + b] = og * tanh_fast(cc);
            }
        }
    }
    __syncthreads();

    // h_last in buffer 0 (TT even): sh[u*32 + b]
    for (int idx = tid; idx < BB * FUT; idx += 512) {
        int bb = idx / FUT;
        int f  = idx % FUT;
        float acc = sblin[f];
        #pragma unroll
        for (int u = 0; u < HL; u++)
            acc += sh[u * 32 + bb] * sWlin[f * HL + u];
        float v = acc > 0.f ? acc : 0.01f * acc;
        out[((size_t)bb * NH + n) * FUT + f] = v;
    }
}

// ---------------------------------------------------------------------------
extern "C" void kernel_launch(void* const* d_in, const int* in_sizes, int n_in,
                              void* d_out, int out_size)
{
    const float* data_meteo = (const float*)d_in[0];
    const float* data_hydro = (const float*)d_in[1];
    const int*   eh         = (const int*)  d_in[2];
    const int*   em         = (const int*)  d_in[3];
    const float* W_rel_m    = (const float*)d_in[4];
    const float* b_rel_m    = (const float*)d_in[5];
    const float* W_root_m   = (const float*)d_in[6];
    const float* W_rel_h    = (const float*)d_in[7];
    const float* b_rel_h    = (const float*)d_in[8];
    const float* W_root_h   = (const float*)d_in[9];
    const float* W_ih       = (const float*)d_in[10];
    const float* W_hh       = (const float*)d_in[11];
    const float* b_ih       = (const float*)d_in[12];
    const float* b_hh       = (const float*)d_in[13];
    const float* W_lin      = (const float*)d_in[14];
    const float* b_lin      = (const float*)d_in[15];

    const int Eh = in_sizes[2] / 2;
    const int Em = in_sizes[3] / 2;

    csr_kernel<<<1, 256>>>(eh, em, Eh, Em);

    gnn_kernel<<<(BB * TT) / TB, 256>>>(data_meteo, data_hydro,
                                        W_rel_m, b_rel_m, W_root_m,
                                        W_rel_h, b_rel_h, W_root_h);

    cudaFuncSetAttribute(xgemm_kernel,
                         cudaFuncAttributeMaxDynamicSharedMemorySize, XG_BYTES);
    dim3 xg(NH, TT / TC);
    xgemm_kernel<<<xg, 256, XG_BYTES>>>(W_ih, b_ih, b_hh);

    cudaFuncSetAttribute(lstm_kernel,
                         cudaFuncAttributeMaxDynamicSharedMemorySize, LS_BYTES);
    lstm_kernel<<<NH, 512, LS_BYTES>>>(W_hh, W_lin, b_lin, (float*)d_out);
}